// round 5
// baseline (speedup 1.0000x reference)
#include <cuda_runtime.h>

#define NN 50000
#define EE 800000

// ---------------- scratch (device globals; no allocation allowed) ----------------
__device__ int    g_is64;               // 1 if edge_index is int64, 0 if int32
__device__ int    g_cnt[NN];            // in-degree (w/o self loop)
__device__ int    g_start[NN];          // CSR offsets
__device__ int    g_cursor[NN];         // fill cursors
__device__ int    g_srcadj[EE];         // CSR adjacency: source node per slot
__device__ float  g_dis[NN];            // rsqrt(deg)
__device__ float4 g_bases[NN * 16];     // [n][64] basis projections
__device__ float  g_w[NN * 32];         // [n][32] combination weights
__device__ float4 g_h1[NN * 32];        // layer1 out [n][128]
__device__ float4 g_h2[NN * 32];        // layer2 out [n][128]
__device__ float4 g_cls[NN];            // per-node {ps0, ps1, pd0, pd1}

// index accessor: edge_index stored as [2, E]; i in [0, 2E)
__device__ __forceinline__ int eidx(const void* ei, int is64, long long i) {
    if (is64) return (int)((const long long*)ei)[i];
    return ((const int*)ei)[i];
}

// ---------------- dtype detection (reads <= 512 bytes, safe for either dtype) ----------
__global__ void k_detect(const void* ei) {
    if (threadIdx.x == 0) {
        const long long* p = (const long long*)ei;
        int is64 = 1;
        for (int i = 0; i < 64; i++) {
            long long v = p[i];
            if (v < 0 || v >= NN) { is64 = 0; break; }
        }
        g_is64 = is64;
    }
}

// ---------------- CSR build ----------------
__global__ void k_zero() {
    int i = blockIdx.x * blockDim.x + threadIdx.x;
    if (i < NN) g_cnt[i] = 0;
}

__global__ void k_hist(const void* __restrict__ ei) {
    int e = blockIdx.x * blockDim.x + threadIdx.x;
    if (e >= EE) return;
    int is64 = g_is64;
    unsigned c = (unsigned)eidx(ei, is64, (long long)EE + e);
    if (c < NN) atomicAdd(&g_cnt[c], 1);
}

// single block, 1024 threads: exclusive scan of g_cnt -> g_start, init cursors
__global__ void k_scan() {
    __shared__ int warpsum[32];
    const int CH = (NN + 1023) / 1024;   // 49
    int t = threadIdx.x;
    int lane = t & 31, w = t >> 5;
    int base = t * CH;
    int sum = 0;
    for (int i = 0; i < CH; i++) {
        int n = base + i;
        if (n < NN) sum += g_cnt[n];
    }
    int v = sum;
    for (int o = 1; o < 32; o <<= 1) {
        int u = __shfl_up_sync(0xffffffffu, v, o);
        if (lane >= o) v += u;
    }
    if (lane == 31) warpsum[w] = v;
    __syncthreads();
    if (w == 0) {
        int s = warpsum[lane];
        for (int o = 1; o < 32; o <<= 1) {
            int u = __shfl_up_sync(0xffffffffu, s, o);
            if (lane >= o) s += u;
        }
        warpsum[lane] = s;
    }
    __syncthreads();
    int run = v - sum + (w > 0 ? warpsum[w - 1] : 0);
    for (int i = 0; i < CH; i++) {
        int n = base + i;
        if (n < NN) {
            g_start[n] = run;
            g_cursor[n] = run;
            run += g_cnt[n];
        }
    }
}

__global__ void k_dis() {
    int i = blockIdx.x * blockDim.x + threadIdx.x;
    if (i < NN) g_dis[i] = rsqrtf((float)(g_cnt[i] + 1));   // +1 self loop
}

__global__ void k_reorder(const void* __restrict__ ei) {
    int e = blockIdx.x * blockDim.x + threadIdx.x;
    if (e >= EE) return;
    int is64 = g_is64;
    unsigned r = (unsigned)eidx(ei, is64, e);
    unsigned c = (unsigned)eidx(ei, is64, (long long)EE + e);
    if (r >= NN || c >= NN) return;
    int slot = atomicAdd(&g_cursor[c], 1);
    g_srcadj[slot] = (int)r;
}

// ---------------- node projection: bases = x@Wb, w = x@Wc + bc ----------------
// Block = 128 threads (4 warps). Warp handles 4 nodes; x rows in registers,
// broadcast via shuffle; W (128x96) staged in smem. NN % 16 == 0, grid exact.
__global__ void k_proj(const float* __restrict__ x_ext, int use_h1,
                       const float* __restrict__ Wb, const float* __restrict__ Wc,
                       const float* __restrict__ bc) {
    __shared__ float sW[128][96];   // 48 KB
    for (int i = threadIdx.x; i < 128 * 96; i += blockDim.x) {
        int k = i / 96, j = i - k * 96;
        sW[k][j] = (j < 64) ? Wb[k * 64 + j] : Wc[k * 32 + (j - 64)];
    }
    __syncthreads();

    const float* __restrict__ x = use_h1 ? (const float*)g_h1 : x_ext;

    int warp = blockIdx.x * (blockDim.x >> 5) + (threadIdx.x >> 5);
    int lane = threadIdx.x & 31;
    int n0 = warp * 4;

    float4 xr[4];
#pragma unroll
    for (int i = 0; i < 4; i++)
        xr[i] = *(const float4*)(x + (size_t)(n0 + i) * 128 + lane * 4);

    float a0[4] = {0,0,0,0}, a1[4] = {0,0,0,0}, a2[4] = {0,0,0,0};

#pragma unroll 4
    for (int k4 = 0; k4 < 32; k4++) {
        float4 xs[4];
#pragma unroll
        for (int i = 0; i < 4; i++) {
            xs[i].x = __shfl_sync(0xffffffffu, xr[i].x, k4);
            xs[i].y = __shfl_sync(0xffffffffu, xr[i].y, k4);
            xs[i].z = __shfl_sync(0xffffffffu, xr[i].z, k4);
            xs[i].w = __shfl_sync(0xffffffffu, xr[i].w, k4);
        }
#pragma unroll
        for (int c = 0; c < 4; c++) {
            int k = k4 * 4 + c;
            float w0 = sW[k][lane], w1 = sW[k][lane + 32], w2 = sW[k][lane + 64];
#pragma unroll
            for (int i = 0; i < 4; i++) {
                float xk = (c == 0) ? xs[i].x : (c == 1) ? xs[i].y : (c == 2) ? xs[i].z : xs[i].w;
                a0[i] += xk * w0;
                a1[i] += xk * w1;
                a2[i] += xk * w2;
            }
        }
    }

    float bcv = bc[lane];
#pragma unroll
    for (int i = 0; i < 4; i++) {
        int n = n0 + i;
        float* bp = (float*)g_bases + (size_t)n * 64;
        bp[lane]      = a0[i];
        bp[lane + 32] = a1[i];
        g_w[(size_t)n * 32 + lane] = a2[i] + bcv;
    }
}

// ---------------- aggregation (gather over CSR) + fused combine ----------------
// One warp per node. acc0/acc1 hold agg[lane], agg[32+lane].
// Then out[n, h*16+f] = bias[o] + sum_b w[n,h,b]*agg[b*16+f] (+relu).
__global__ void k_agg(const float* __restrict__ bias, int to_h2, int relu) {
    __shared__ float sm[4][64];
    int wi = threadIdx.x >> 5;
    int lane = threadIdx.x & 31;
    int n = blockIdx.x * 4 + wi;            // grid exact: NN/4 blocks

    float dn = g_dis[n];
    float s = dn * dn;
    const float* __restrict__ bs = (const float*)g_bases;

    float acc0 = bs[(size_t)n * 64 + lane] * s;         // self loop
    float acc1 = bs[(size_t)n * 64 + 32 + lane] * s;

    int start = g_start[n];
    int end = start + g_cnt[n];
    int i = start;
    for (; i + 2 <= end; i += 2) {
        int s0 = g_srcadj[i], s1 = g_srcadj[i + 1];
        float n0 = g_dis[s0] * dn, n1 = g_dis[s1] * dn;
        float b00 = bs[(size_t)s0 * 64 + lane],      b10 = bs[(size_t)s1 * 64 + lane];
        float b01 = bs[(size_t)s0 * 64 + 32 + lane], b11 = bs[(size_t)s1 * 64 + 32 + lane];
        acc0 += b00 * n0 + b10 * n1;
        acc1 += b01 * n0 + b11 * n1;
    }
    if (i < end) {
        int s0 = g_srcadj[i];
        float n0 = g_dis[s0] * dn;
        acc0 += bs[(size_t)s0 * 64 + lane] * n0;
        acc1 += bs[(size_t)s0 * 64 + 32 + lane] * n0;
    }

    sm[wi][lane] = acc0;
    sm[wi][32 + lane] = acc1;
    __syncwarp();

    float wreg = g_w[(size_t)n * 32 + lane];
    float* __restrict__ out = (float*)(to_h2 ? g_h2 : g_h1) + (size_t)n * 128;

#pragma unroll
    for (int j = 0; j < 4; j++) {
        int o = lane + 32 * j;
        int h = o >> 4, f = o & 15;
        float v = bias[o];
#pragma unroll
        for (int b = 0; b < 4; b++) {
            float wb = __shfl_sync(0xffffffffu, wreg, h * 4 + b);
            v += wb * sm[wi][b * 16 + f];
        }
        if (relu) v = fmaxf(v, 0.f);
        out[o] = v;
    }
}

// ---------------- classifier node projection: {h2·Wcls[:128], h2·Wcls[128:]} ------------
__global__ void k_cls_proj(const float* __restrict__ Wcls) {
    __shared__ float sW[512];
    for (int i = threadIdx.x; i < 512; i += blockDim.x) sW[i] = Wcls[i];
    __syncthreads();
    int n = blockIdx.x * blockDim.x + threadIdx.x;
    if (n >= NN) return;
    float4 acc = make_float4(0.f, 0.f, 0.f, 0.f);
#pragma unroll
    for (int k4 = 0; k4 < 32; k4++) {
        float4 hv = g_h2[n * 32 + k4];
#pragma unroll
        for (int c = 0; c < 4; c++) {
            int k = k4 * 4 + c;
            float hc = (c == 0) ? hv.x : (c == 1) ? hv.y : (c == 2) ? hv.z : hv.w;
            acc.x += hc * sW[k * 2];
            acc.y += hc * sW[k * 2 + 1];
            acc.z += hc * sW[256 + k * 2];
            acc.w += hc * sW[256 + k * 2 + 1];
        }
    }
    g_cls[n] = acc;
}

// ---------------- per-edge output: ps[src] + pd[dst] + bcls ----------------
__global__ void k_edge_out(const void* __restrict__ ei,
                           const float* __restrict__ bcls,
                           float2* __restrict__ out) {
    int e = blockIdx.x * blockDim.x + threadIdx.x;
    if (e >= EE) return;
    int is64 = g_is64;
    unsigned s = (unsigned)eidx(ei, is64, e);
    unsigned d = (unsigned)eidx(ei, is64, (long long)EE + e);
    float4 ps = (s < NN) ? g_cls[s] : make_float4(0, 0, 0, 0);
    float4 pd = (d < NN) ? g_cls[d] : make_float4(0, 0, 0, 0);
    out[e] = make_float2(ps.x + pd.z + bcls[0], ps.y + pd.w + bcls[1]);
}

// ---------------- launch ----------------
extern "C" void kernel_launch(void* const* d_in, const int* in_sizes, int n_in,
                              void* d_out, int out_size) {
    const float* x    = (const float*)d_in[0];
    const void*  ei   = d_in[1];
    const float* Wb1  = (const float*)d_in[2];
    const float* Wc1  = (const float*)d_in[3];
    const float* bc1  = (const float*)d_in[4];
    const float* b1   = (const float*)d_in[5];
    const float* Wb2  = (const float*)d_in[6];
    const float* Wc2  = (const float*)d_in[7];
    const float* bc2  = (const float*)d_in[8];
    const float* b2   = (const float*)d_in[9];
    const float* Wcls = (const float*)d_in[10];
    const float* bcls = (const float*)d_in[11];
    float2*      out  = (float2*)d_out;

    // dtype detect + CSR build + symnorm
    k_detect<<<1, 32>>>(ei);
    k_zero<<<(NN + 255) / 256, 256>>>();
    k_hist<<<(EE + 255) / 256, 256>>>(ei);
    k_scan<<<1, 1024>>>();
    k_dis<<<(NN + 255) / 256, 256>>>();
    k_reorder<<<(EE + 255) / 256, 256>>>(ei);

    // layer 1
    k_proj<<<NN / 16, 128>>>(x, 0, Wb1, Wc1, bc1);
    k_agg<<<NN / 4, 128>>>(b1, /*to_h2=*/0, /*relu=*/1);

    // layer 2
    k_proj<<<NN / 16, 128>>>(x, 1, Wb2, Wc2, bc2);
    k_agg<<<NN / 4, 128>>>(b2, /*to_h2=*/1, /*relu=*/0);

    // edge classifier
    k_cls_proj<<<(NN + 127) / 128, 128>>>(Wcls);
    k_edge_out<<<(EE + 255) / 256, 256>>>(ei, bcls, out);
}

// round 6
// speedup vs baseline: 1.2336x; 1.2336x over previous
#include <cuda_runtime.h>

#define NN 50000
#define EE 800000
#define NB ((NN + 255) / 256)   // 196 scan blocks

// ---------------- scratch (device globals; no allocation allowed) ----------------
__device__ int    g_is64;               // 1 if edge_index is int64, 0 if int32
__device__ int    g_cnt[NN];            // in-degree (w/o self loop)
__device__ int    g_start[NN];          // CSR offsets
__device__ int    g_cursor[NN];         // fill cursors
__device__ int    g_part[NB];           // per-block count sums
__device__ int    g_poff[NB];           // exclusive offsets of block sums
__device__ int    g_srcadj[EE];         // CSR adjacency: source node per slot
__device__ float  g_dis[NN];            // rsqrt(deg)
__device__ float4 g_bases[NN * 16];     // [n][64] basis projections
__device__ float  g_w[NN * 32];         // [n][32] combination weights
__device__ float4 g_h1[NN * 32];        // layer1 out [n][128]
__device__ float4 g_h2[NN * 32];        // layer2 out [n][128]
__device__ float4 g_cls[NN];            // per-node {ps0, ps1, pd0, pd1}

// index accessor: edge_index stored as [2, E]; i in [0, 2E)
__device__ __forceinline__ int eidx(const void* ei, int is64, long long i) {
    if (is64) return (int)((const long long*)ei)[i];
    return ((const int*)ei)[i];
}

// ---------------- init: zero counts + dtype detection ----------------
__global__ void k_init(const void* ei) {
    int i = blockIdx.x * blockDim.x + threadIdx.x;
    if (i < NN) g_cnt[i] = 0;
    if (i == 0) {
        const long long* p = (const long long*)ei;
        int is64 = 1;
        for (int k = 0; k < 64; k++) {
            long long v = p[k];
            if (v < 0 || v >= NN) { is64 = 0; break; }
        }
        g_is64 = is64;
    }
}

// ---------------- histogram ----------------
__global__ void k_hist(const void* __restrict__ ei) {
    int e = blockIdx.x * blockDim.x + threadIdx.x;
    if (e >= EE) return;
    int is64 = g_is64;
    unsigned c = (unsigned)eidx(ei, is64, (long long)EE + e);
    if (c < NN) atomicAdd(&g_cnt[c], 1);
}

// ---------------- 3-phase scan ----------------
__device__ __forceinline__ int block_incl_scan(int v, int lane, int warp, int* wsum) {
#pragma unroll
    for (int o = 1; o < 32; o <<= 1) {
        int u = __shfl_up_sync(0xffffffffu, v, o);
        if (lane >= o) v += u;
    }
    if (lane == 31) wsum[warp] = v;
    __syncthreads();
    if (warp == 0) {
        int s = (lane < 8) ? wsum[lane] : 0;
#pragma unroll
        for (int o = 1; o < 8; o <<= 1) {
            int u = __shfl_up_sync(0xffffffffu, s, o);
            if (lane >= o) s += u;
        }
        if (lane < 8) wsum[lane] = s;
    }
    __syncthreads();
    if (warp > 0) v += wsum[warp - 1];
    return v;
}

__global__ void k_blocksum() {
    __shared__ int wsum[8];
    int i = blockIdx.x * 256 + threadIdx.x;
    int lane = threadIdx.x & 31, warp = threadIdx.x >> 5;
    int v = (i < NN) ? g_cnt[i] : 0;
#pragma unroll
    for (int o = 16; o > 0; o >>= 1) v += __shfl_down_sync(0xffffffffu, v, o);
    if (lane == 0) wsum[warp] = v;
    __syncthreads();
    if (threadIdx.x == 0) {
        int s = 0;
#pragma unroll
        for (int w = 0; w < 8; w++) s += wsum[w];
        g_part[blockIdx.x] = s;
    }
}

__global__ void k_scanpart() {   // 1 block, 256 threads (NB=196 <= 256)
    __shared__ int wsum[8];
    int t = threadIdx.x;
    int lane = t & 31, warp = t >> 5;
    int v = (t < NB) ? g_part[t] : 0;
    int incl = block_incl_scan(v, lane, warp, wsum);
    if (t < NB) g_poff[t] = incl - v;   // exclusive
}

__global__ void k_offsets() {    // writes start, cursor, dis
    __shared__ int wsum[8];
    int i = blockIdx.x * 256 + threadIdx.x;
    int lane = threadIdx.x & 31, warp = threadIdx.x >> 5;
    int c = (i < NN) ? g_cnt[i] : 0;
    int incl = block_incl_scan(c, lane, warp, wsum);
    int excl = incl - c + g_poff[blockIdx.x];
    if (i < NN) {
        g_start[i] = excl;
        g_cursor[i] = excl;
        g_dis[i] = rsqrtf((float)(c + 1));   // +1 self loop
    }
}

// ---------------- reorder into CSR ----------------
__global__ void k_reorder(const void* __restrict__ ei) {
    int e = blockIdx.x * blockDim.x + threadIdx.x;
    if (e >= EE) return;
    int is64 = g_is64;
    unsigned r = (unsigned)eidx(ei, is64, e);
    unsigned c = (unsigned)eidx(ei, is64, (long long)EE + e);
    if (r >= NN || c >= NN) return;
    int slot = atomicAdd(&g_cursor[c], 1);
    g_srcadj[slot] = (int)r;
}

// ---------------- node projection: bases = x@Wb, w = x@Wc + bc ----------------
// Block = 128 threads (4 warps). Warp handles 4 nodes; x rows in registers,
// broadcast via shuffle; W (128x96) staged in smem. NN % 16 == 0, grid exact.
__global__ void k_proj(const float* __restrict__ x_ext, int use_h1,
                       const float* __restrict__ Wb, const float* __restrict__ Wc,
                       const float* __restrict__ bc) {
    __shared__ float sW[128][96];   // 48 KB
    for (int i = threadIdx.x; i < 128 * 96; i += blockDim.x) {
        int k = i / 96, j = i - k * 96;
        sW[k][j] = (j < 64) ? Wb[k * 64 + j] : Wc[k * 32 + (j - 64)];
    }
    __syncthreads();

    const float* __restrict__ x = use_h1 ? (const float*)g_h1 : x_ext;

    int warp = blockIdx.x * (blockDim.x >> 5) + (threadIdx.x >> 5);
    int lane = threadIdx.x & 31;
    int n0 = warp * 4;

    float4 xr[4];
#pragma unroll
    for (int i = 0; i < 4; i++)
        xr[i] = *(const float4*)(x + (size_t)(n0 + i) * 128 + lane * 4);

    float a0[4] = {0,0,0,0}, a1[4] = {0,0,0,0}, a2[4] = {0,0,0,0};

#pragma unroll 4
    for (int k4 = 0; k4 < 32; k4++) {
        float4 xs[4];
#pragma unroll
        for (int i = 0; i < 4; i++) {
            xs[i].x = __shfl_sync(0xffffffffu, xr[i].x, k4);
            xs[i].y = __shfl_sync(0xffffffffu, xr[i].y, k4);
            xs[i].z = __shfl_sync(0xffffffffu, xr[i].z, k4);
            xs[i].w = __shfl_sync(0xffffffffu, xr[i].w, k4);
        }
#pragma unroll
        for (int c = 0; c < 4; c++) {
            int k = k4 * 4 + c;
            float w0 = sW[k][lane], w1 = sW[k][lane + 32], w2 = sW[k][lane + 64];
#pragma unroll
            for (int i = 0; i < 4; i++) {
                float xk = (c == 0) ? xs[i].x : (c == 1) ? xs[i].y : (c == 2) ? xs[i].z : xs[i].w;
                a0[i] += xk * w0;
                a1[i] += xk * w1;
                a2[i] += xk * w2;
            }
        }
    }

    float bcv = bc[lane];
#pragma unroll
    for (int i = 0; i < 4; i++) {
        int n = n0 + i;
        float* bp = (float*)g_bases + (size_t)n * 64;
        bp[lane]      = a0[i];
        bp[lane + 32] = a1[i];
        g_w[(size_t)n * 32 + lane] = a2[i] + bcv;
    }
}

// ---------------- aggregation (gather over CSR) + fused combine ----------------
// One warp per node. acc0/acc1 hold agg[lane], agg[32+lane].
// Then out[n, h*16+f] = bias[o] + sum_b w[n,h,b]*agg[b*16+f] (+relu).
__global__ void k_agg(const float* __restrict__ bias, int to_h2, int relu) {
    __shared__ float sm[4][64];
    int wi = threadIdx.x >> 5;
    int lane = threadIdx.x & 31;
    int n = blockIdx.x * 4 + wi;            // grid exact: NN/4 blocks

    float dn = g_dis[n];
    float s = dn * dn;
    const float* __restrict__ bs = (const float*)g_bases;

    float acc0 = bs[(size_t)n * 64 + lane] * s;         // self loop
    float acc1 = bs[(size_t)n * 64 + 32 + lane] * s;

    int start = g_start[n];
    int end = start + g_cnt[n];
    int i = start;
    for (; i + 2 <= end; i += 2) {
        int s0 = g_srcadj[i], s1 = g_srcadj[i + 1];
        float n0 = g_dis[s0] * dn, n1 = g_dis[s1] * dn;
        float b00 = bs[(size_t)s0 * 64 + lane],      b10 = bs[(size_t)s1 * 64 + lane];
        float b01 = bs[(size_t)s0 * 64 + 32 + lane], b11 = bs[(size_t)s1 * 64 + 32 + lane];
        acc0 += b00 * n0 + b10 * n1;
        acc1 += b01 * n0 + b11 * n1;
    }
    if (i < end) {
        int s0 = g_srcadj[i];
        float n0 = g_dis[s0] * dn;
        acc0 += bs[(size_t)s0 * 64 + lane] * n0;
        acc1 += bs[(size_t)s0 * 64 + 32 + lane] * n0;
    }

    sm[wi][lane] = acc0;
    sm[wi][32 + lane] = acc1;
    __syncwarp();

    float wreg = g_w[(size_t)n * 32 + lane];
    float* __restrict__ out = (float*)(to_h2 ? g_h2 : g_h1) + (size_t)n * 128;

#pragma unroll
    for (int j = 0; j < 4; j++) {
        int o = lane + 32 * j;
        int h = o >> 4, f = o & 15;
        float v = bias[o];
#pragma unroll
        for (int b = 0; b < 4; b++) {
            float wb = __shfl_sync(0xffffffffu, wreg, h * 4 + b);
            v += wb * sm[wi][b * 16 + f];
        }
        if (relu) v = fmaxf(v, 0.f);
        out[o] = v;
    }
}

// ---------------- classifier node projection: {h2·Wcls[:128], h2·Wcls[128:]} ------------
__global__ void k_cls_proj(const float* __restrict__ Wcls) {
    __shared__ float sW[512];
    for (int i = threadIdx.x; i < 512; i += blockDim.x) sW[i] = Wcls[i];
    __syncthreads();
    int n = blockIdx.x * blockDim.x + threadIdx.x;
    if (n >= NN) return;
    float4 acc = make_float4(0.f, 0.f, 0.f, 0.f);
#pragma unroll
    for (int k4 = 0; k4 < 32; k4++) {
        float4 hv = g_h2[n * 32 + k4];
#pragma unroll
        for (int c = 0; c < 4; c++) {
            int k = k4 * 4 + c;
            float hc = (c == 0) ? hv.x : (c == 1) ? hv.y : (c == 2) ? hv.z : hv.w;
            acc.x += hc * sW[k * 2];
            acc.y += hc * sW[k * 2 + 1];
            acc.z += hc * sW[256 + k * 2];
            acc.w += hc * sW[256 + k * 2 + 1];
        }
    }
    g_cls[n] = acc;
}

// ---------------- per-edge output: ps[src] + pd[dst] + bcls ----------------
__global__ void k_edge_out(const void* __restrict__ ei,
                           const float* __restrict__ bcls,
                           float2* __restrict__ out) {
    int e = blockIdx.x * blockDim.x + threadIdx.x;
    if (e >= EE) return;
    int is64 = g_is64;
    unsigned s = (unsigned)eidx(ei, is64, e);
    unsigned d = (unsigned)eidx(ei, is64, (long long)EE + e);
    float4 ps = (s < NN) ? g_cls[s] : make_float4(0, 0, 0, 0);
    float4 pd = (d < NN) ? g_cls[d] : make_float4(0, 0, 0, 0);
    out[e] = make_float2(ps.x + pd.z + bcls[0], ps.y + pd.w + bcls[1]);
}

// ---------------- launch ----------------
extern "C" void kernel_launch(void* const* d_in, const int* in_sizes, int n_in,
                              void* d_out, int out_size) {
    const float* x    = (const float*)d_in[0];
    const void*  ei   = d_in[1];
    const float* Wb1  = (const float*)d_in[2];
    const float* Wc1  = (const float*)d_in[3];
    const float* bc1  = (const float*)d_in[4];
    const float* b1   = (const float*)d_in[5];
    const float* Wb2  = (const float*)d_in[6];
    const float* Wc2  = (const float*)d_in[7];
    const float* bc2  = (const float*)d_in[8];
    const float* b2   = (const float*)d_in[9];
    const float* Wcls = (const float*)d_in[10];
    const float* bcls = (const float*)d_in[11];
    float2*      out  = (float2*)d_out;

    // CSR build + symnorm
    k_init<<<NB, 256>>>(ei);
    k_hist<<<(EE + 255) / 256, 256>>>(ei);
    k_blocksum<<<NB, 256>>>();
    k_scanpart<<<1, 256>>>();
    k_offsets<<<NB, 256>>>();
    k_reorder<<<(EE + 255) / 256, 256>>>(ei);

    // layer 1
    k_proj<<<NN / 16, 128>>>(x, 0, Wb1, Wc1, bc1);
    k_agg<<<NN / 4, 128>>>(b1, /*to_h2=*/0, /*relu=*/1);

    // layer 2
    k_proj<<<NN / 16, 128>>>(x, 1, Wb2, Wc2, bc2);
    k_agg<<<NN / 4, 128>>>(b2, /*to_h2=*/1, /*relu=*/0);

    // edge classifier
    k_cls_proj<<<(NN + 127) / 128, 128>>>(Wcls);
    k_edge_out<<<(EE + 255) / 256, 256>>>(ei, bcls, out);
}

// round 7
// speedup vs baseline: 1.9867x; 1.6105x over previous
#include <cuda_runtime.h>

#define NN 50000
#define EE 800000
#define NB ((NN + 255) / 256)   // 196 scan blocks
#define PJB 300                  // persistent proj blocks

// ---------------- scratch (device globals; no allocation allowed) ----------------
__device__ int    g_is64;               // 1 if edge_index is int64, 0 if int32
__device__ int    g_cnt[NN];            // in-degree (w/o self loop)
__device__ int    g_start[NN];          // CSR offsets
__device__ int    g_cursor[NN];         // fill cursors
__device__ int    g_part[NB];           // per-block count sums
__device__ int    g_srcadj[EE];         // CSR adjacency: source node per slot
__device__ float  g_dis[NN];            // rsqrt(deg)
__device__ float4 g_bases[NN * 16];     // [n][64] basis projections, PRE-SCALED by dis[n]
__device__ float  g_w[NN * 32];         // [n][32] combination weights
__device__ float4 g_h1[NN * 32];        // layer1 out [n][128]
__device__ float4 g_cls[NN];            // per-node {ps0, ps1, pd0, pd1}

// index accessor: edge_index stored as [2, E]; i in [0, 2E)
__device__ __forceinline__ int eidx(const void* ei, int is64, long long i) {
    if (is64) return (int)((const long long*)ei)[i];
    return ((const int*)ei)[i];
}

// ---------------- init: zero counts + dtype detection ----------------
__global__ void k_init(const void* ei) {
    int i = blockIdx.x * blockDim.x + threadIdx.x;
    if (i < NN) g_cnt[i] = 0;
    if (i == 0) {
        const long long* p = (const long long*)ei;
        int is64 = 1;
        for (int k = 0; k < 64; k++) {
            long long v = p[k];
            if (v < 0 || v >= NN) { is64 = 0; break; }
        }
        g_is64 = is64;
    }
}

// ---------------- histogram ----------------
__global__ void k_hist(const void* __restrict__ ei) {
    int e = blockIdx.x * blockDim.x + threadIdx.x;
    if (e >= EE) return;
    int is64 = g_is64;
    unsigned c = (unsigned)eidx(ei, is64, (long long)EE + e);
    if (c < NN) atomicAdd(&g_cnt[c], 1);
}

// ---------------- block sums ----------------
__global__ void k_blocksum() {
    __shared__ int wsum[8];
    int i = blockIdx.x * 256 + threadIdx.x;
    int lane = threadIdx.x & 31, warp = threadIdx.x >> 5;
    int v = (i < NN) ? g_cnt[i] : 0;
#pragma unroll
    for (int o = 16; o > 0; o >>= 1) v += __shfl_down_sync(0xffffffffu, v, o);
    if (lane == 0) wsum[warp] = v;
    __syncthreads();
    if (threadIdx.x == 0) {
        int s = 0;
#pragma unroll
        for (int w = 0; w < 8; w++) s += wsum[w];
        g_part[blockIdx.x] = s;
    }
}

// ---------------- offsets: inline partial-scan + per-element scan + dis ----------------
__device__ __forceinline__ int block_incl_scan(int v, int lane, int warp, int* wsum) {
#pragma unroll
    for (int o = 1; o < 32; o <<= 1) {
        int u = __shfl_up_sync(0xffffffffu, v, o);
        if (lane >= o) v += u;
    }
    if (lane == 31) wsum[warp] = v;
    __syncthreads();
    if (warp == 0) {
        int s = (lane < 8) ? wsum[lane] : 0;
#pragma unroll
        for (int o = 1; o < 8; o <<= 1) {
            int u = __shfl_up_sync(0xffffffffu, s, o);
            if (lane >= o) s += u;
        }
        if (lane < 8) wsum[lane] = s;
    }
    __syncthreads();
    if (warp > 0) v += wsum[warp - 1];
    return v;
}

__global__ void k_offsets() {
    __shared__ int wred[8];
    __shared__ int wsum[8];
    __shared__ int s_poff;
    int t = threadIdx.x, lane = t & 31, warp = t >> 5;
    // block offset = sum of g_part[j] for j < blockIdx.x  (blockIdx.x < NB <= 256)
    int pv = (t < blockIdx.x) ? g_part[t] : 0;
#pragma unroll
    for (int o = 16; o > 0; o >>= 1) pv += __shfl_down_sync(0xffffffffu, pv, o);
    if (lane == 0) wred[warp] = pv;
    __syncthreads();
    if (t == 0) {
        int s = 0;
#pragma unroll
        for (int w = 0; w < 8; w++) s += wred[w];
        s_poff = s;
    }
    __syncthreads();

    int i = blockIdx.x * 256 + t;
    int c = (i < NN) ? g_cnt[i] : 0;
    int incl = block_incl_scan(c, lane, warp, wsum);
    int excl = incl - c + s_poff;
    if (i < NN) {
        g_start[i] = excl;
        g_cursor[i] = excl;
        g_dis[i] = rsqrtf((float)(c + 1));   // +1 self loop
    }
}

// ---------------- reorder into CSR ----------------
__global__ void k_reorder(const void* __restrict__ ei) {
    int e = blockIdx.x * blockDim.x + threadIdx.x;
    if (e >= EE) return;
    int is64 = g_is64;
    unsigned r = (unsigned)eidx(ei, is64, e);
    unsigned c = (unsigned)eidx(ei, is64, (long long)EE + e);
    if (r >= NN || c >= NN) return;
    int slot = atomicAdd(&g_cursor[c], 1);
    g_srcadj[slot] = (int)r;
}

// ---------------- node projection (persistent): bases' = (x@Wb)*dis, w = x@Wc + bc ------
// 300 blocks x 256 threads; W staged once per block; warps grid-stride over 4-node groups.
__global__ __launch_bounds__(256) void k_proj(
        const float* __restrict__ x_ext, int use_h1,
        const float* __restrict__ Wb, const float* __restrict__ Wc,
        const float* __restrict__ bc) {
    __shared__ float sW[128][96];   // 48 KB
    for (int i = threadIdx.x; i < 128 * 96; i += 256) {
        int k = i / 96, j = i - k * 96;
        sW[k][j] = (j < 64) ? Wb[k * 64 + j] : Wc[k * 32 + (j - 64)];
    }
    __syncthreads();

    const float* __restrict__ x = use_h1 ? (const float*)g_h1 : x_ext;

    int warp = threadIdx.x >> 5;
    int lane = threadIdx.x & 31;
    float bcv = bc[lane];

    for (int g = blockIdx.x * 8 + warp; g < NN / 4; g += PJB * 8) {
        int n0 = g * 4;

        float4 xr[4];
#pragma unroll
        for (int i = 0; i < 4; i++)
            xr[i] = *(const float4*)(x + (size_t)(n0 + i) * 128 + lane * 4);

        float a0[4] = {0,0,0,0}, a1[4] = {0,0,0,0}, a2[4] = {0,0,0,0};

#pragma unroll 4
        for (int k4 = 0; k4 < 32; k4++) {
            float4 xs[4];
#pragma unroll
            for (int i = 0; i < 4; i++) {
                xs[i].x = __shfl_sync(0xffffffffu, xr[i].x, k4);
                xs[i].y = __shfl_sync(0xffffffffu, xr[i].y, k4);
                xs[i].z = __shfl_sync(0xffffffffu, xr[i].z, k4);
                xs[i].w = __shfl_sync(0xffffffffu, xr[i].w, k4);
            }
#pragma unroll
            for (int c = 0; c < 4; c++) {
                int k = k4 * 4 + c;
                float w0 = sW[k][lane], w1 = sW[k][lane + 32], w2 = sW[k][lane + 64];
#pragma unroll
                for (int i = 0; i < 4; i++) {
                    float xk = (c == 0) ? xs[i].x : (c == 1) ? xs[i].y : (c == 2) ? xs[i].z : xs[i].w;
                    a0[i] += xk * w0;
                    a1[i] += xk * w1;
                    a2[i] += xk * w2;
                }
            }
        }

#pragma unroll
        for (int i = 0; i < 4; i++) {
            int n = n0 + i;
            float dis = g_dis[n];
            float* bp = (float*)g_bases + (size_t)n * 64;
            bp[lane]      = a0[i] * dis;
            bp[lane + 32] = a1[i] * dis;
            g_w[(size_t)n * 32 + lane] = a2[i] + bcv;
        }
    }
}

// ---------------- aggregation (vectorized gather) + fused combine (+cls for layer 2) ----
// One warp per node. Half-warp per edge, one float4 per lane -> one LDG.128 covers 2 edges.
// agg = dis[n] * (bases'[n] + sum bases'[src]).  mode 0: write h1 (+relu). mode 1: cls.
__global__ void k_agg(const float* __restrict__ bias, const float* __restrict__ Wcls,
                      int mode) {
    __shared__ float sm[4][64];
    __shared__ float sWc[512];
    if (mode == 1) {
        for (int i = threadIdx.x; i < 512; i += 128) sWc[i] = Wcls[i];
    }
    __syncthreads();

    int wi = threadIdx.x >> 5;
    int lane = threadIdx.x & 31;
    int half = lane >> 4, hl = lane & 15;
    int n = blockIdx.x * 4 + wi;            // grid exact: NN/4 blocks

    float dn = g_dis[n];
    const float4* __restrict__ bp4 = (const float4*)g_bases;

    float4 acc;
    if (half == 0) acc = bp4[(size_t)n * 16 + hl];          // self loop (bases' already *dis)
    else           acc = make_float4(0.f, 0.f, 0.f, 0.f);

    int start = g_start[n];
    int end = start + g_cnt[n];
    int i = start;
    for (; i + 2 <= end; i += 2) {
        int s = g_srcadj[i + half];
        float4 v = bp4[(size_t)s * 16 + hl];
        acc.x += v.x; acc.y += v.y; acc.z += v.z; acc.w += v.w;
    }
    if (i < end && half == 0) {
        int s = g_srcadj[i];
        float4 v = bp4[(size_t)s * 16 + hl];
        acc.x += v.x; acc.y += v.y; acc.z += v.z; acc.w += v.w;
    }

    // fold the two halves; every lane ends with the full sum for its element quad
    acc.x += __shfl_xor_sync(0xffffffffu, acc.x, 16);
    acc.y += __shfl_xor_sync(0xffffffffu, acc.y, 16);
    acc.z += __shfl_xor_sync(0xffffffffu, acc.z, 16);
    acc.w += __shfl_xor_sync(0xffffffffu, acc.w, 16);

    if (half == 0) {
        float4 sc = make_float4(acc.x * dn, acc.y * dn, acc.z * dn, acc.w * dn);
        ((float4*)sm[wi])[hl] = sc;
    }
    __syncwarp();

    float wreg = g_w[(size_t)n * 32 + lane];

    if (mode == 0) {
        float* __restrict__ out = (float*)g_h1 + (size_t)n * 128;
#pragma unroll
        for (int j = 0; j < 4; j++) {
            int o = lane + 32 * j;
            int h = o >> 4, f = o & 15;
            float v = bias[o];
#pragma unroll
            for (int b = 0; b < 4; b++) {
                float wb = __shfl_sync(0xffffffffu, wreg, h * 4 + b);
                v += wb * sm[wi][b * 16 + f];
            }
            out[o] = fmaxf(v, 0.f);
        }
    } else {
        float c0 = 0.f, c1 = 0.f, c2 = 0.f, c3 = 0.f;
#pragma unroll
        for (int j = 0; j < 4; j++) {
            int o = lane + 32 * j;
            int h = o >> 4, f = o & 15;
            float v = bias[o];
#pragma unroll
            for (int b = 0; b < 4; b++) {
                float wb = __shfl_sync(0xffffffffu, wreg, h * 4 + b);
                v += wb * sm[wi][b * 16 + f];
            }
            c0 += v * sWc[o * 2];
            c1 += v * sWc[o * 2 + 1];
            c2 += v * sWc[256 + o * 2];
            c3 += v * sWc[256 + o * 2 + 1];
        }
#pragma unroll
        for (int o = 16; o > 0; o >>= 1) {
            c0 += __shfl_down_sync(0xffffffffu, c0, o);
            c1 += __shfl_down_sync(0xffffffffu, c1, o);
            c2 += __shfl_down_sync(0xffffffffu, c2, o);
            c3 += __shfl_down_sync(0xffffffffu, c3, o);
        }
        if (lane == 0) g_cls[n] = make_float4(c0, c1, c2, c3);
    }
}

// ---------------- per-edge output: ps[src] + pd[dst] + bcls ----------------
__global__ void k_edge_out(const void* __restrict__ ei,
                           const float* __restrict__ bcls,
                           float2* __restrict__ out) {
    int e = blockIdx.x * blockDim.x + threadIdx.x;
    if (e >= EE) return;
    int is64 = g_is64;
    unsigned s = (unsigned)eidx(ei, is64, e);
    unsigned d = (unsigned)eidx(ei, is64, (long long)EE + e);
    float4 ps = (s < NN) ? g_cls[s] : make_float4(0, 0, 0, 0);
    float4 pd = (d < NN) ? g_cls[d] : make_float4(0, 0, 0, 0);
    out[e] = make_float2(ps.x + pd.z + bcls[0], ps.y + pd.w + bcls[1]);
}

// ---------------- launch ----------------
extern "C" void kernel_launch(void* const* d_in, const int* in_sizes, int n_in,
                              void* d_out, int out_size) {
    const float* x    = (const float*)d_in[0];
    const void*  ei   = d_in[1];
    const float* Wb1  = (const float*)d_in[2];
    const float* Wc1  = (const float*)d_in[3];
    const float* bc1  = (const float*)d_in[4];
    const float* b1   = (const float*)d_in[5];
    const float* Wb2  = (const float*)d_in[6];
    const float* Wc2  = (const float*)d_in[7];
    const float* bc2  = (const float*)d_in[8];
    const float* b2   = (const float*)d_in[9];
    const float* Wcls = (const float*)d_in[10];
    const float* bcls = (const float*)d_in[11];
    float2*      out  = (float2*)d_out;

    // CSR build + symnorm
    k_init<<<NB, 256>>>(ei);
    k_hist<<<(EE + 255) / 256, 256>>>(ei);
    k_blocksum<<<NB, 256>>>();
    k_offsets<<<NB, 256>>>();
    k_reorder<<<(EE + 255) / 256, 256>>>(ei);

    // layer 1
    k_proj<<<PJB, 256>>>(x, 0, Wb1, Wc1, bc1);
    k_agg<<<NN / 4, 128>>>(b1, Wcls, /*mode=*/0);

    // layer 2 (fused classifier projection; h2 never materialized)
    k_proj<<<PJB, 256>>>(x, 1, Wb2, Wc2, bc2);
    k_agg<<<NN / 4, 128>>>(b2, Wcls, /*mode=*/1);

    // edge classifier output
    k_edge_out<<<(EE + 255) / 256, 256>>>(ei, bcls, out);
}

// round 8
// speedup vs baseline: 2.0086x; 1.0110x over previous
#include <cuda_runtime.h>

#define NN 50000
#define EE 800000
#define NB ((NN + 255) / 256)   // 196 scan blocks
#define PJB 300                  // persistent proj blocks

typedef unsigned long long u64;

__device__ __forceinline__ u64 pk2(float lo, float hi) {
    u64 d; asm("mov.b64 %0, {%1,%2};" : "=l"(d) : "f"(lo), "f"(hi)); return d;
}
__device__ __forceinline__ void upk2(u64 v, float& lo, float& hi) {
    asm("mov.b64 {%0,%1}, %2;" : "=f"(lo), "=f"(hi) : "l"(v));
}
__device__ __forceinline__ u64 f2fma(u64 a, u64 b, u64 c) {
    u64 d; asm("fma.rn.f32x2 %0, %1, %2, %3;" : "=l"(d) : "l"(a), "l"(b), "l"(c)); return d;
}

// ---------------- scratch (device globals; no allocation allowed) ----------------
__device__ int    g_is64;               // 1 if edge_index is int64, 0 if int32
__device__ int    g_cnt[NN];            // in-degree (w/o self loop)
__device__ int    g_start[NN];          // CSR offsets
__device__ int    g_cursor[NN];         // fill cursors
__device__ int    g_part[NB];           // per-block count sums
__device__ int    g_srcadj[EE];         // CSR adjacency: source node per slot
__device__ float  g_dis[NN];            // rsqrt(deg)
__device__ float4 g_bases[NN * 16];     // [n][64] basis projections, PRE-SCALED by dis[n]
__device__ float  g_w[NN * 32];         // [n][32] combination weights
__device__ float4 g_h1[NN * 32];        // layer1 out [n][128]
__device__ float4 g_cls[NN];            // per-node {ps0, ps1, pd0, pd1}

// index accessor: edge_index stored as [2, E]; i in [0, 2E)
__device__ __forceinline__ int eidx(const void* ei, int is64, long long i) {
    if (is64) return (int)((const long long*)ei)[i];
    return ((const int*)ei)[i];
}

// ---------------- init: zero counts + dtype detection ----------------
__global__ void k_init(const void* ei) {
    int i = blockIdx.x * blockDim.x + threadIdx.x;
    if (i < NN) g_cnt[i] = 0;
    if (i == 0) {
        const long long* p = (const long long*)ei;
        int is64 = 1;
        for (int k = 0; k < 64; k++) {
            long long v = p[k];
            if (v < 0 || v >= NN) { is64 = 0; break; }
        }
        g_is64 = is64;
    }
}

// ---------------- histogram ----------------
__global__ void k_hist(const void* __restrict__ ei) {
    int e = blockIdx.x * blockDim.x + threadIdx.x;
    if (e >= EE) return;
    int is64 = g_is64;
    unsigned c = (unsigned)eidx(ei, is64, (long long)EE + e);
    if (c < NN) atomicAdd(&g_cnt[c], 1);
}

// ---------------- block sums ----------------
__global__ void k_blocksum() {
    __shared__ int wsum[8];
    int i = blockIdx.x * 256 + threadIdx.x;
    int lane = threadIdx.x & 31, warp = threadIdx.x >> 5;
    int v = (i < NN) ? g_cnt[i] : 0;
#pragma unroll
    for (int o = 16; o > 0; o >>= 1) v += __shfl_down_sync(0xffffffffu, v, o);
    if (lane == 0) wsum[warp] = v;
    __syncthreads();
    if (threadIdx.x == 0) {
        int s = 0;
#pragma unroll
        for (int w = 0; w < 8; w++) s += wsum[w];
        g_part[blockIdx.x] = s;
    }
}

// ---------------- offsets: inline partial-scan + per-element scan + dis ----------------
__device__ __forceinline__ int block_incl_scan(int v, int lane, int warp, int* wsum) {
#pragma unroll
    for (int o = 1; o < 32; o <<= 1) {
        int u = __shfl_up_sync(0xffffffffu, v, o);
        if (lane >= o) v += u;
    }
    if (lane == 31) wsum[warp] = v;
    __syncthreads();
    if (warp == 0) {
        int s = (lane < 8) ? wsum[lane] : 0;
#pragma unroll
        for (int o = 1; o < 8; o <<= 1) {
            int u = __shfl_up_sync(0xffffffffu, s, o);
            if (lane >= o) s += u;
        }
        if (lane < 8) wsum[lane] = s;
    }
    __syncthreads();
    if (warp > 0) v += wsum[warp - 1];
    return v;
}

__global__ void k_offsets() {
    __shared__ int wred[8];
    __shared__ int wsum[8];
    __shared__ int s_poff;
    int t = threadIdx.x, lane = t & 31, warp = t >> 5;
    int pv = (t < blockIdx.x) ? g_part[t] : 0;
#pragma unroll
    for (int o = 16; o > 0; o >>= 1) pv += __shfl_down_sync(0xffffffffu, pv, o);
    if (lane == 0) wred[warp] = pv;
    __syncthreads();
    if (t == 0) {
        int s = 0;
#pragma unroll
        for (int w = 0; w < 8; w++) s += wred[w];
        s_poff = s;
    }
    __syncthreads();

    int i = blockIdx.x * 256 + t;
    int c = (i < NN) ? g_cnt[i] : 0;
    int incl = block_incl_scan(c, lane, warp, wsum);
    int excl = incl - c + s_poff;
    if (i < NN) {
        g_start[i] = excl;
        g_cursor[i] = excl;
        g_dis[i] = rsqrtf((float)(c + 1));   // +1 self loop
    }
}

// ---------------- reorder into CSR ----------------
__global__ void k_reorder(const void* __restrict__ ei) {
    int e = blockIdx.x * blockDim.x + threadIdx.x;
    if (e >= EE) return;
    int is64 = g_is64;
    unsigned r = (unsigned)eidx(ei, is64, e);
    unsigned c = (unsigned)eidx(ei, is64, (long long)EE + e);
    if (r >= NN || c >= NN) return;
    int slot = atomicAdd(&g_cursor[c], 1);
    g_srcadj[slot] = (int)r;
}

// ---------------- node projection (persistent, f32x2 packed) ----------------
// bases' = (x@Wb)*dis, w = x@Wc + bc. 300 blocks x 256 threads; W staged once;
// warps grid-stride over 4-node groups. Node-pair f32x2 accumulators: the packed
// multiplier (x_i[k], x_{i+1}[k]) is built once per (k, pair) and reused for all
// three output groups; weights duplicated (w,w) per k. Halves FMA-pipe ops.
__global__ __launch_bounds__(256) void k_proj(
        const float* __restrict__ x_ext, int use_h1,
        const float* __restrict__ Wb, const float* __restrict__ Wc,
        const float* __restrict__ bc) {
    __shared__ float sW[128][96];   // 48 KB
    for (int i = threadIdx.x; i < 128 * 96; i += 256) {
        int k = i / 96, j = i - k * 96;
        sW[k][j] = (j < 64) ? Wb[k * 64 + j] : Wc[k * 32 + (j - 64)];
    }
    __syncthreads();

    const float* __restrict__ x = use_h1 ? (const float*)g_h1 : x_ext;

    int warp = threadIdx.x >> 5;
    int lane = threadIdx.x & 31;
    float bcv = bc[lane];

    for (int g = blockIdx.x * 8 + warp; g < NN / 4; g += PJB * 8) {
        int n0 = g * 4;

        float4 xr[4];
#pragma unroll
        for (int i = 0; i < 4; i++)
            xr[i] = *(const float4*)(x + (size_t)(n0 + i) * 128 + lane * 4);

        u64 a0p[2] = {0, 0}, a1p[2] = {0, 0}, a2p[2] = {0, 0};

#pragma unroll 4
        for (int k4 = 0; k4 < 32; k4++) {
            float4 xs[4];
#pragma unroll
            for (int i = 0; i < 4; i++) {
                xs[i].x = __shfl_sync(0xffffffffu, xr[i].x, k4);
                xs[i].y = __shfl_sync(0xffffffffu, xr[i].y, k4);
                xs[i].z = __shfl_sync(0xffffffffu, xr[i].z, k4);
                xs[i].w = __shfl_sync(0xffffffffu, xr[i].w, k4);
            }
#pragma unroll
            for (int c = 0; c < 4; c++) {
                int k = k4 * 4 + c;
                float w0 = sW[k][lane], w1 = sW[k][lane + 32], w2 = sW[k][lane + 64];
                u64 w0d = pk2(w0, w0), w1d = pk2(w1, w1), w2d = pk2(w2, w2);
                float xc0 = (c == 0) ? xs[0].x : (c == 1) ? xs[0].y : (c == 2) ? xs[0].z : xs[0].w;
                float xc1 = (c == 0) ? xs[1].x : (c == 1) ? xs[1].y : (c == 2) ? xs[1].z : xs[1].w;
                float xc2 = (c == 0) ? xs[2].x : (c == 1) ? xs[2].y : (c == 2) ? xs[2].z : xs[2].w;
                float xc3 = (c == 0) ? xs[3].x : (c == 1) ? xs[3].y : (c == 2) ? xs[3].z : xs[3].w;
                u64 xp0 = pk2(xc0, xc1), xp1 = pk2(xc2, xc3);
                a0p[0] = f2fma(xp0, w0d, a0p[0]);
                a0p[1] = f2fma(xp1, w0d, a0p[1]);
                a1p[0] = f2fma(xp0, w1d, a1p[0]);
                a1p[1] = f2fma(xp1, w1d, a1p[1]);
                a2p[0] = f2fma(xp0, w2d, a2p[0]);
                a2p[1] = f2fma(xp1, w2d, a2p[1]);
            }
        }

        float a0[4], a1[4], a2[4];
        upk2(a0p[0], a0[0], a0[1]); upk2(a0p[1], a0[2], a0[3]);
        upk2(a1p[0], a1[0], a1[1]); upk2(a1p[1], a1[2], a1[3]);
        upk2(a2p[0], a2[0], a2[1]); upk2(a2p[1], a2[2], a2[3]);

#pragma unroll
        for (int i = 0; i < 4; i++) {
            int n = n0 + i;
            float dis = g_dis[n];
            float* bp = (float*)g_bases + (size_t)n * 64;
            bp[lane]      = a0[i] * dis;
            bp[lane + 32] = a1[i] * dis;
            g_w[(size_t)n * 32 + lane] = a2[i] + bcv;
        }
    }
}

// ---------------- aggregation (vectorized gather) + fused combine (+cls for layer 2) ----
__global__ void k_agg(const float* __restrict__ bias, const float* __restrict__ Wcls,
                      int mode) {
    __shared__ float sm[4][64];
    __shared__ float sWc[512];
    if (mode == 1) {
        for (int i = threadIdx.x; i < 512; i += 128) sWc[i] = Wcls[i];
    }
    __syncthreads();

    int wi = threadIdx.x >> 5;
    int lane = threadIdx.x & 31;
    int half = lane >> 4, hl = lane & 15;
    int n = blockIdx.x * 4 + wi;            // grid exact: NN/4 blocks

    float dn = g_dis[n];
    const float4* __restrict__ bp4 = (const float4*)g_bases;

    float4 acc;
    if (half == 0) acc = bp4[(size_t)n * 16 + hl];          // self loop (bases' already *dis)
    else           acc = make_float4(0.f, 0.f, 0.f, 0.f);

    int start = g_start[n];
    int end = start + g_cnt[n];
    int i = start;
    for (; i + 2 <= end; i += 2) {
        int s = g_srcadj[i + half];
        float4 v = bp4[(size_t)s * 16 + hl];
        acc.x += v.x; acc.y += v.y; acc.z += v.z; acc.w += v.w;
    }
    if (i < end && half == 0) {
        int s = g_srcadj[i];
        float4 v = bp4[(size_t)s * 16 + hl];
        acc.x += v.x; acc.y += v.y; acc.z += v.z; acc.w += v.w;
    }

    acc.x += __shfl_xor_sync(0xffffffffu, acc.x, 16);
    acc.y += __shfl_xor_sync(0xffffffffu, acc.y, 16);
    acc.z += __shfl_xor_sync(0xffffffffu, acc.z, 16);
    acc.w += __shfl_xor_sync(0xffffffffu, acc.w, 16);

    if (half == 0) {
        float4 sc = make_float4(acc.x * dn, acc.y * dn, acc.z * dn, acc.w * dn);
        ((float4*)sm[wi])[hl] = sc;
    }
    __syncwarp();

    float wreg = g_w[(size_t)n * 32 + lane];

    if (mode == 0) {
        float* __restrict__ out = (float*)g_h1 + (size_t)n * 128;
#pragma unroll
        for (int j = 0; j < 4; j++) {
            int o = lane + 32 * j;
            int h = o >> 4, f = o & 15;
            float v = bias[o];
#pragma unroll
            for (int b = 0; b < 4; b++) {
                float wb = __shfl_sync(0xffffffffu, wreg, h * 4 + b);
                v += wb * sm[wi][b * 16 + f];
            }
            out[o] = fmaxf(v, 0.f);
        }
    } else {
        float c0 = 0.f, c1 = 0.f, c2 = 0.f, c3 = 0.f;
#pragma unroll
        for (int j = 0; j < 4; j++) {
            int o = lane + 32 * j;
            int h = o >> 4, f = o & 15;
            float v = bias[o];
#pragma unroll
            for (int b = 0; b < 4; b++) {
                float wb = __shfl_sync(0xffffffffu, wreg, h * 4 + b);
                v += wb * sm[wi][b * 16 + f];
            }
            c0 += v * sWc[o * 2];
            c1 += v * sWc[o * 2 + 1];
            c2 += v * sWc[256 + o * 2];
            c3 += v * sWc[256 + o * 2 + 1];
        }
#pragma unroll
        for (int o = 16; o > 0; o >>= 1) {
            c0 += __shfl_down_sync(0xffffffffu, c0, o);
            c1 += __shfl_down_sync(0xffffffffu, c1, o);
            c2 += __shfl_down_sync(0xffffffffu, c2, o);
            c3 += __shfl_down_sync(0xffffffffu, c3, o);
        }
        if (lane == 0) g_cls[n] = make_float4(c0, c1, c2, c3);
    }
}

// ---------------- per-edge output (2 edges/thread): ps[src] + pd[dst] + bcls ------------
__global__ void k_edge_out(const void* __restrict__ ei,
                           const float* __restrict__ bcls,
                           float4* __restrict__ out2) {
    int p = blockIdx.x * blockDim.x + threadIdx.x;   // pair index, < EE/2
    if (p >= EE / 2) return;
    int is64 = g_is64;
    unsigned s0, s1, d0, d1;
    if (is64) {
        longlong2 sp = ((const longlong2*)ei)[p];
        longlong2 dp = ((const longlong2*)ei)[EE / 2 + p];
        s0 = (unsigned)sp.x; s1 = (unsigned)sp.y;
        d0 = (unsigned)dp.x; d1 = (unsigned)dp.y;
    } else {
        int2 sp = ((const int2*)ei)[p];
        int2 dp = ((const int2*)ei)[EE / 2 + p];
        s0 = (unsigned)sp.x; s1 = (unsigned)sp.y;
        d0 = (unsigned)dp.x; d1 = (unsigned)dp.y;
    }
    float b0 = bcls[0], b1 = bcls[1];
    float4 ps0 = (s0 < NN) ? g_cls[s0] : make_float4(0, 0, 0, 0);
    float4 pd0 = (d0 < NN) ? g_cls[d0] : make_float4(0, 0, 0, 0);
    float4 ps1 = (s1 < NN) ? g_cls[s1] : make_float4(0, 0, 0, 0);
    float4 pd1 = (d1 < NN) ? g_cls[d1] : make_float4(0, 0, 0, 0);
    out2[p] = make_float4(ps0.x + pd0.z + b0, ps0.y + pd0.w + b1,
                          ps1.x + pd1.z + b0, ps1.y + pd1.w + b1);
}

// ---------------- launch ----------------
extern "C" void kernel_launch(void* const* d_in, const int* in_sizes, int n_in,
                              void* d_out, int out_size) {
    const float* x    = (const float*)d_in[0];
    const void*  ei   = d_in[1];
    const float* Wb1  = (const float*)d_in[2];
    const float* Wc1  = (const float*)d_in[3];
    const float* bc1  = (const float*)d_in[4];
    const float* b1   = (const float*)d_in[5];
    const float* Wb2  = (const float*)d_in[6];
    const float* Wc2  = (const float*)d_in[7];
    const float* bc2  = (const float*)d_in[8];
    const float* b2   = (const float*)d_in[9];
    const float* Wcls = (const float*)d_in[10];
    const float* bcls = (const float*)d_in[11];
    float4*      out  = (float4*)d_out;

    // CSR build + symnorm
    k_init<<<NB, 256>>>(ei);
    k_hist<<<(EE + 255) / 256, 256>>>(ei);
    k_blocksum<<<NB, 256>>>();
    k_offsets<<<NB, 256>>>();
    k_reorder<<<(EE + 255) / 256, 256>>>(ei);

    // layer 1
    k_proj<<<PJB, 256>>>(x, 0, Wb1, Wc1, bc1);
    k_agg<<<NN / 4, 128>>>(b1, Wcls, /*mode=*/0);

    // layer 2 (fused classifier projection; h2 never materialized)
    k_proj<<<PJB, 256>>>(x, 1, Wb2, Wc2, bc2);
    k_agg<<<NN / 4, 128>>>(b2, Wcls, /*mode=*/1);

    // edge classifier output
    k_edge_out<<<(EE / 2 + 255) / 256, 256>>>(ei, bcls, out);
}